// round 2
// baseline (speedup 1.0000x reference)
#include <cuda_runtime.h>
#include <math.h>

#define B_    8
#define N_    1024
#define DIM_  768
#define H_    8
#define HD_   96
#define E_    24
#define NT    (B_*N_)      /* 8192 tokens */
#define NA    (NT*H_)      /* 65536 assignments */
#define SCALE_ 0.10206207261596575f  /* 96^-0.5 */

/* ------------------------- scratch (device globals) ------------------------- */
__device__ float g_gate[NA];
__device__ float g_me[E_];
__device__ float g_z;
__device__ int   g_ecount[E_];
__device__ int   g_elist[E_*NA];                 /* per-expert assignment lists */
__device__ float g_k[NT*HD_];
__device__ float g_v[NT*HD_];
__device__ float g_q[(size_t)NA*HD_];
__device__ float g_o[(size_t)NA*HD_];

/* ------------------------------- zero counters ------------------------------ */
__global__ void zero_kernel() {
    int i = threadIdx.x;
    if (i < E_) { g_me[i] = 0.f; g_ecount[i] = 0; }
    if (i == 0) g_z = 0.f;
}

__global__ void zero_out_kernel(float* __restrict__ out, int n) {
    int i = blockIdx.x * 256 + threadIdx.x;
    if (i < n) out[i] = 0.f;
}

/* --------------------- gating: logits, softmax, top-8, lists ---------------- */
/* 1024 blocks x 256 threads; 1 warp per token, 8 tokens per block */
__global__ void gate_kernel(const float* __restrict__ x,
                            const float* __restrict__ Wg,
                            const int*   __restrict__ task_p) {
    __shared__ float sme[E_];
    __shared__ float sz;
    __shared__ int   scnt[E_];
    __shared__ int   sbase[E_];
    int tid  = threadIdx.x;
    int warp = tid >> 5;
    int lane = tid & 31;
    int t = blockIdx.x * 8 + warp;

    if (tid < E_) { sme[tid] = 0.f; scnt[tid] = 0; }
    if (tid == 0) sz = 0.f;
    __syncthreads();

    int task = *task_p;
    const float* wg = Wg + (size_t)task * DIM_ * E_;
    const float* xr = x + (size_t)t * DIM_;

    float acc = 0.f;
    if (lane < E_) {
        #pragma unroll 4
        for (int d = 0; d < DIM_; d++) acc += xr[d] * wg[d * E_ + lane];
    }
    float logit = (lane < E_) ? acc : -1e30f;

    /* softmax over 24 experts */
    float m = logit;
    #pragma unroll
    for (int o = 16; o >= 1; o >>= 1) m = fmaxf(m, __shfl_xor_sync(0xffffffffu, m, o));
    float p = (lane < E_) ? expf(logit - m) : 0.f;
    float s = p;
    #pragma unroll
    for (int o = 16; o >= 1; o >>= 1) s += __shfl_xor_sync(0xffffffffu, s, o);
    float prob = p / s;
    float lse = m + logf(s);
    if (lane == 0) atomicAdd(&sz, lse * lse);
    if (lane < E_) atomicAdd(&sme[lane], prob);

    /* top-8: iterative warp argmax; ballot lowest lane breaks ties (jax order) */
    float val = (lane < E_) ? prob : -1.f;
    float sel_g = 0.f; int sel_e = 0;
    #pragma unroll
    for (int it = 0; it < H_; it++) {
        float mm = val;
        #pragma unroll
        for (int o = 16; o >= 1; o >>= 1) mm = fmaxf(mm, __shfl_xor_sync(0xffffffffu, mm, o));
        unsigned msk = __ballot_sync(0xffffffffu, val == mm);
        int src = __ffs(msk) - 1;
        if (lane == src) val = -1.f;
        if (lane == it) { sel_e = src; sel_g = mm; }
    }
    float gv = (lane < H_) ? sel_g : 0.f;
    #pragma unroll
    for (int o = 16; o >= 1; o >>= 1) gv += __shfl_xor_sync(0xffffffffu, gv, o);
    float denom = gv + 1e-6f;

    int pos = 0;
    if (lane < H_) pos = atomicAdd(&scnt[sel_e], 1);
    __syncthreads();
    if (tid < E_) sbase[tid] = atomicAdd(&g_ecount[tid], scnt[tid]);
    __syncthreads();
    if (lane < H_) {
        int a = t * H_ + lane;
        g_gate[a] = sel_g / denom;
        g_elist[sel_e * NA + sbase[sel_e] + pos] = a;
    }
    if (tid < E_) atomicAdd(&g_me[tid], sme[tid]);
    if (tid == 0) atomicAdd(&g_z, sz);
}

/* ----------------------- kv projection: x @ Wkv + b ------------------------- */
/* tile 64x64, grid (128, 3), 256 threads, 4x4 per-thread */
__global__ void kv_kernel(const float* __restrict__ x,
                          const float* __restrict__ Wkv,
                          const float* __restrict__ bkv) {
    __shared__ float xsT[32][68];
    __shared__ float ws[32][68];
    int r0 = blockIdx.x * 64;
    int c0 = blockIdx.y * 64;
    int tid = threadIdx.x;
    int ty = tid >> 4, tx = tid & 15;
    float acc[4][4] = {};

    for (int k0 = 0; k0 < DIM_; k0 += 32) {
        for (int i = tid; i < 64 * 32; i += 256) {
            int r = i >> 5, k = i & 31;
            xsT[k][r] = x[(size_t)(r0 + r) * DIM_ + k0 + k];
        }
        for (int i = tid; i < 32 * 64; i += 256) {
            int k = i >> 6, c = i & 63;
            ws[k][c] = Wkv[(size_t)(k0 + k) * (2 * HD_) + c0 + c];
        }
        __syncthreads();
        #pragma unroll
        for (int k = 0; k < 32; k++) {
            float4 a4 = *(const float4*)&xsT[k][ty * 4];
            float4 b4 = *(const float4*)&ws[k][tx * 4];
            float av[4] = {a4.x, a4.y, a4.z, a4.w};
            float bv[4] = {b4.x, b4.y, b4.z, b4.w};
            #pragma unroll
            for (int i = 0; i < 4; i++)
                #pragma unroll
                for (int j = 0; j < 4; j++) acc[i][j] += av[i] * bv[j];
        }
        __syncthreads();
    }
    #pragma unroll
    for (int i = 0; i < 4; i++) {
        int r = r0 + ty * 4 + i;
        #pragma unroll
        for (int j = 0; j < 4; j++) {
            int c = c0 + tx * 4 + j;
            float v = acc[i][j] + bkv[c];
            if (c < HD_) g_k[(size_t)r * HD_ + c]          = v;
            else         g_v[(size_t)r * HD_ + (c - HD_)]  = v;
        }
    }
}

/* ------------- grouped q projection: per-expert gathered GEMM --------------- */
/* tile: 64 assignments x 96 cols, grid (1024, 24), 256 threads, 4x6 per-thread */
__global__ void q_kernel(const float* __restrict__ x,
                         const float* __restrict__ W1) {
    int e = blockIdx.y;
    int count = g_ecount[e];
    int base = blockIdx.x * 64;
    if (base >= count) return;

    __shared__ float xsT[32][68];
    __shared__ float ws[32][100];
    __shared__ int   s_a[64];
    int tid = threadIdx.x;
    if (tid < 64) {
        int idx = base + tid; if (idx >= count) idx = count - 1;
        s_a[tid] = g_elist[e * NA + idx];
    }
    __syncthreads();

    int ty = tid >> 4, tx = tid & 15;
    float acc[4][6] = {};
    const float* w1 = W1 + (size_t)e * DIM_ * HD_;

    for (int k0 = 0; k0 < DIM_; k0 += 32) {
        for (int i = tid; i < 64 * 32; i += 256) {
            int r = i >> 5, k = i & 31;
            int tok = s_a[r] >> 3;
            xsT[k][r] = x[(size_t)tok * DIM_ + k0 + k];
        }
        for (int i = tid; i < 32 * 96; i += 256) {
            int k = i / 96, c = i % 96;
            ws[k][c] = w1[(size_t)(k0 + k) * HD_ + c];
        }
        __syncthreads();
        #pragma unroll
        for (int k = 0; k < 32; k++) {
            float4 a4 = *(const float4*)&xsT[k][ty * 4];
            float av[4] = {a4.x, a4.y, a4.z, a4.w};
            float bv[6];
            #pragma unroll
            for (int j = 0; j < 6; j++) bv[j] = ws[k][tx + 16 * j];
            #pragma unroll
            for (int i = 0; i < 4; i++)
                #pragma unroll
                for (int j = 0; j < 6; j++) acc[i][j] += av[i] * bv[j];
        }
        __syncthreads();
    }
    #pragma unroll
    for (int i = 0; i < 4; i++) {
        int r = ty * 4 + i;
        if (base + r < count) {
            int a = s_a[r];
            #pragma unroll
            for (int j = 0; j < 6; j++) g_q[(size_t)a * HD_ + tx + 16 * j] = acc[i][j];
        }
    }
}

/* ------------------- fused flash attention (S never stored) ----------------- */
/* grid (16 row-tiles, 64 bh), 256 threads, dynamic smem 95232 B               */
#define ATTN_SMEM_FLOATS (2*96*68 + 64*100 + 64*68)
__global__ void attn_kernel() {
    extern __shared__ float sm[];
    float (*qT)[68]  = (float(*)[68]) sm;                       /* [96][68] */
    float (*kT)[68]  = (float(*)[68])(sm + 96*68);              /* [96][68] */
    float (*vs)[100] = (float(*)[100])(sm + 2*96*68);           /* [64][100] */
    float (*ps)[68]  = (float(*)[68])(sm + 2*96*68 + 64*100);   /* [64][68] */

    int it = blockIdx.x, bh = blockIdx.y;
    int b = bh >> 3, h = bh & 7;
    int i0 = it * 64;
    int tid = threadIdx.x;
    int ty = tid >> 4, tx = tid & 15;

    /* load Q tile (transposed) */
    for (int idx = tid; idx < 64 * 96; idx += 256) {
        int i = idx / 96, d = idx % 96;
        qT[d][i] = g_q[((size_t)(b * N_ + i0 + i) * H_ + h) * HD_ + d];
    }

    float m_i[4], l_i[4], o_acc[4][6];
    #pragma unroll
    for (int i = 0; i < 4; i++) {
        m_i[i] = -1e30f; l_i[i] = 0.f;
        #pragma unroll
        for (int c = 0; c < 6; c++) o_acc[i][c] = 0.f;
    }

    for (int jt = 0; jt < 16; jt++) {
        int j0 = jt * 64;
        __syncthreads();   /* previous iter's PV reads done; qT load done (it 0) */
        for (int idx = tid; idx < 64 * 96; idx += 256) {
            int j = idx / 96, d = idx % 96;
            float kvp = g_k[(size_t)(b * N_ + j0 + j) * HD_ + d];
            kT[d][j] = kvp;
            vs[j][d] = g_v[(size_t)(b * N_ + j0 + j) * HD_ + d];
        }
        __syncthreads();

        /* S tile = Q K^T * scale (4x4 per thread) */
        float sv[4][4] = {};
        #pragma unroll 8
        for (int d = 0; d < 96; d++) {
            float4 a4 = *(const float4*)&qT[d][ty * 4];
            float4 b4 = *(const float4*)&kT[d][tx * 4];
            float av[4] = {a4.x, a4.y, a4.z, a4.w};
            float bv[4] = {b4.x, b4.y, b4.z, b4.w};
            #pragma unroll
            for (int i = 0; i < 4; i++)
                #pragma unroll
                for (int j = 0; j < 4; j++) sv[i][j] += av[i] * bv[j];
        }

        /* online softmax update per row */
        #pragma unroll
        for (int i = 0; i < 4; i++) {
            float rmax = -1e30f;
            #pragma unroll
            for (int j = 0; j < 4; j++) { sv[i][j] *= SCALE_; rmax = fmaxf(rmax, sv[i][j]); }
            #pragma unroll
            for (int o = 8; o >= 1; o >>= 1)
                rmax = fmaxf(rmax, __shfl_xor_sync(0xffffffffu, rmax, o, 16));
            float nm = fmaxf(m_i[i], rmax);
            float corr = __expf(m_i[i] - nm);
            float rsum = 0.f;
            #pragma unroll
            for (int j = 0; j < 4; j++) { sv[i][j] = __expf(sv[i][j] - nm); rsum += sv[i][j]; }
            #pragma unroll
            for (int o = 8; o >= 1; o >>= 1)
                rsum += __shfl_xor_sync(0xffffffffu, rsum, o, 16);
            l_i[i] = l_i[i] * corr + rsum;
            m_i[i] = nm;
            #pragma unroll
            for (int c = 0; c < 6; c++) o_acc[i][c] *= corr;
            /* store P transposed: ps[j][i] */
            #pragma unroll
            for (int j = 0; j < 4; j++) ps[tx * 4 + j][ty * 4 + i] = sv[i][j];
        }
        __syncthreads();

        /* O += P V (4 rows x 6 cols per thread) */
        #pragma unroll 8
        for (int j = 0; j < 64; j++) {
            float4 a4 = *(const float4*)&ps[j][ty * 4];
            float av[4] = {a4.x, a4.y, a4.z, a4.w};
            float bv[6];
            #pragma unroll
            for (int c = 0; c < 6; c++) bv[c] = vs[j][tx + 16 * c];
            #pragma unroll
            for (int i = 0; i < 4; i++)
                #pragma unroll
                for (int c = 0; c < 6; c++) o_acc[i][c] += av[i] * bv[c];
        }
    }

    #pragma unroll
    for (int i = 0; i < 4; i++) {
        float inv = 1.f / l_i[i];
        int tok = b * N_ + i0 + ty * 4 + i;
        #pragma unroll
        for (int c = 0; c < 6; c++)
            g_o[((size_t)tok * H_ + h) * HD_ + tx + 16 * c] = o_acc[i][c] * inv;
    }
}

/* ---- grouped reduce: out[t] += gate[a] * o[a] @ W2[e]  (atomic combine) ---- */
/* per block: 32 assignments x 768 cols (6 col-tiles of 128), grid (2048, 24)   */
__global__ void reduce_kernel(const float* __restrict__ W2,
                              float* __restrict__ out) {
    int e = blockIdx.y;
    int count = g_ecount[e];
    int base = blockIdx.x * 32;
    if (base >= count) return;

    __shared__ float osT[96][36];
    __shared__ float ws[32][132];
    __shared__ int   s_a[32];
    int tid = threadIdx.x;
    if (tid < 32) {
        int idx = base + tid; if (idx >= count) idx = count - 1;
        s_a[tid] = g_elist[e * NA + idx];
    }
    __syncthreads();

    /* load gated o rows once (transposed) */
    for (int idx = tid; idx < 32 * 96; idx += 256) {
        int r = idx / 96, d = idx % 96;
        int a = s_a[r];
        osT[d][r] = g_gate[a] * g_o[(size_t)a * HD_ + d];
    }
    __syncthreads();

    int ty = tid >> 5, tx = tid & 31;  /* 8 x 32 thread grid -> 4x4 tiles */
    const float* w2 = W2 + (size_t)e * HD_ * DIM_;

    for (int ct = 0; ct < 6; ct++) {
        float acc[4][4] = {};
        for (int k0 = 0; k0 < HD_; k0 += 32) {
            for (int idx = tid; idx < 32 * 128; idx += 256) {
                int k = idx >> 7, c = idx & 127;
                ws[k][c] = w2[(size_t)(k0 + k) * DIM_ + ct * 128 + c];
            }
            __syncthreads();
            #pragma unroll
            for (int k = 0; k < 32; k++) {
                float4 a4 = *(const float4*)&osT[k0 + k][ty * 4];
                float4 b4 = *(const float4*)&ws[k][tx * 4];
                float av[4] = {a4.x, a4.y, a4.z, a4.w};
                float bv[4] = {b4.x, b4.y, b4.z, b4.w};
                #pragma unroll
                for (int i = 0; i < 4; i++)
                    #pragma unroll
                    for (int j = 0; j < 4; j++) acc[i][j] += av[i] * bv[j];
            }
            __syncthreads();
        }
        #pragma unroll
        for (int i = 0; i < 4; i++) {
            int r = ty * 4 + i;
            if (base + r < count) {
                int t = s_a[r] >> 3;
                #pragma unroll
                for (int j = 0; j < 4; j++)
                    atomicAdd(&out[(size_t)t * DIM_ + ct * 128 + tx * 4 + j], acc[i][j]);
            }
        }
    }
}

/* ------------------------------- aux loss ----------------------------------- */
__global__ void aux_kernel(float* __restrict__ out, int out_size) {
    if (threadIdx.x == 0) {
        float mesum = 0.f;
        for (int e = 0; e < E_; e++) mesum += g_me[e];
        float sw = 0.f;
        for (int e = 0; e < E_; e++)
            sw += (g_me[e] / mesum) * ((float)g_ecount[e] / (float)NA);
        sw *= (float)E_;
        float z = g_z / (float)NT;
        float aux = 0.1f * sw + 0.001f * z;
        if (out_size > NT * DIM_) out[out_size - 1] = aux;
    }
}

/* -------------------------------- launch ------------------------------------ */
extern "C" void kernel_launch(void* const* d_in, const int* in_sizes, int n_in,
                              void* d_out, int out_size) {
    const float* x    = (const float*)d_in[0];
    const float* Wg   = (const float*)d_in[1];
    const float* W1   = (const float*)d_in[2];
    const float* W2   = (const float*)d_in[3];
    const float* Wkv  = (const float*)d_in[4];
    const float* bkv  = (const float*)d_in[5];
    const int*   task = (const int*)d_in[6];
    float* out = (float*)d_out;

    cudaFuncSetAttribute(attn_kernel,
                         cudaFuncAttributeMaxDynamicSharedMemorySize,
                         ATTN_SMEM_FLOATS * (int)sizeof(float));

    zero_kernel<<<1, 32>>>();
    zero_out_kernel<<<(out_size + 255) / 256, 256>>>(out, out_size);
    gate_kernel<<<NT / 8, 256>>>(x, Wg, task);
    kv_kernel<<<dim3(NT / 64, 3), 256>>>(x, Wkv, bkv);
    q_kernel<<<dim3(1024, E_), 256>>>(x, W1);
    attn_kernel<<<dim3(16, B_ * H_), 256, ATTN_SMEM_FLOATS * sizeof(float)>>>();
    reduce_kernel<<<dim3(2048, E_), 256>>>(W2, out);
    aux_kernel<<<1, 32>>>(out, out_size);
}